// round 1
// baseline (speedup 1.0000x reference)
#include <cuda_runtime.h>
#include <cuda_bf16.h>

#define N_NODES 100000
#define N_EDGES 1600000
#define F 64
#define N_PAD 100096  // multiple of 64 (= 64 * 1564)

// ---------------- scratch (static device globals; no allocs) ----------------
__device__ float g_el[N_NODES];
__device__ float g_er[N_NODES];
__device__ float g_m[N_NODES];      // segment max (float bits), init -inf
__device__ float g_s[N_NODES];      // segment sum -> reciprocal in place
__device__ float g_w[N_EDGES];      // e, then exp(e - m[dst])
__device__ float g_agg[N_PAD * F];  // feature-space aggregation

// ---------------- init: zero agg, m=-inf, s=0 ----------------
__global__ void k_init() {
    int i = blockIdx.x * blockDim.x + threadIdx.x;
    if (i < N_PAD * F) g_agg[i] = 0.0f;
    if (i < N_NODES) {
        g_m[i] = __int_as_float(0xFF800000);  // -inf
        g_s[i] = 0.0f;
    }
}

// ---------------- el/er: warp per node ----------------
__global__ void k_elr(const float* __restrict__ feat,
                      const float* __restrict__ al,
                      const float* __restrict__ ar) {
    int t = blockIdx.x * blockDim.x + threadIdx.x;
    int node = t >> 5;
    int lane = t & 31;
    if (node >= N_NODES) return;
    float2 f = *(const float2*)(feat + node * F + lane * 2);
    float2 a = *(const float2*)(al + lane * 2);
    float2 r = *(const float2*)(ar + lane * 2);
    float pl = f.x * a.x + f.y * a.y;
    float pr = f.x * r.x + f.y * r.y;
    #pragma unroll
    for (int off = 16; off; off >>= 1) {
        pl += __shfl_down_sync(0xFFFFFFFFu, pl, off);
        pr += __shfl_down_sync(0xFFFFFFFFu, pr, off);
    }
    if (lane == 0) {
        g_el[node] = pl;
        g_er[node] = pr;
    }
}

// ---------------- edge pass 1: e = leakyrelu, segment max ----------------
// float atomic max via int/uint ordering trick (native REDG, no CAS loop)
__global__ void k_edge_max(const int* __restrict__ src,
                           const int* __restrict__ dst) {
    int i = blockIdx.x * blockDim.x + threadIdx.x;
    if (i >= N_EDGES) return;
    int s = src[i], d = dst[i];
    float e = g_el[s] + g_er[d];
    e = (e >= 0.0f) ? e : 0.01f * e;
    g_w[i] = e;
    if (e >= 0.0f)
        atomicMax((int*)&g_m[d], __float_as_int(e));
    else
        atomicMin((unsigned int*)&g_m[d], __float_as_uint(e));
}

// ---------------- edge pass 2: w = exp(e - m[dst]), segment sum ----------------
__global__ void k_edge_exp(const int* __restrict__ dst) {
    int i = blockIdx.x * blockDim.x + threadIdx.x;
    if (i >= N_EDGES) return;
    int d = dst[i];
    float w = __expf(g_w[i] - g_m[d]);
    g_w[i] = w;
    atomicAdd(&g_s[d], w);
}

// ---------------- reciprocal (guard empty destinations) ----------------
__global__ void k_recip() {
    int i = blockIdx.x * blockDim.x + threadIdx.x;
    if (i >= N_NODES) return;
    float s = g_s[i];
    g_s[i] = (s > 0.0f) ? 1.0f / s : 0.0f;
}

// ---------------- scatter: agg[dst] += (w/s[dst]) * feat[src] ----------------
// 16 threads per edge, float4 gather + red.global.add.v4.f32
__global__ void k_scatter(const float* __restrict__ feat,
                          const int* __restrict__ src,
                          const int* __restrict__ dst) {
    int t = blockIdx.x * blockDim.x + threadIdx.x;
    int e = t >> 4;
    int q = t & 15;
    if (e >= N_EDGES) return;
    int s = src[e], d = dst[e];
    float c = g_w[e] * g_s[d];  // g_s holds reciprocal now
    float4 v = *(const float4*)(feat + s * F + q * 4);
    v.x *= c; v.y *= c; v.z *= c; v.w *= c;
    float* p = g_agg + d * F + q * 4;
    asm volatile("red.global.add.v4.f32 [%0], {%1, %2, %3, %4};"
                 :: "l"(p), "f"(v.x), "f"(v.y), "f"(v.z), "f"(v.w)
                 : "memory");
}

// ---------------- final GEMM: out = agg @ W ----------------
// 64 nodes per block, 256 threads: thread owns output col j = tid&63,
// row-group r = tid>>6 (16 nodes each). W column held in registers.
__global__ void k_gemm(const float* __restrict__ W,
                       float* __restrict__ out) {
    __shared__ float fsh[64 * F];
    int tid = threadIdx.x;
    int j = tid & 63;
    int r = tid >> 6;

    float wj[64];
    #pragma unroll
    for (int k = 0; k < 64; k++) wj[k] = W[k * 64 + j];

    int nb = blockIdx.x * 64;
    float4* fsh4 = (float4*)fsh;
    const float4* a4 = (const float4*)(g_agg + nb * F);
    #pragma unroll
    for (int it = 0; it < 4; it++) fsh4[tid + it * 256] = a4[tid + it * 256];
    __syncthreads();

    #pragma unroll
    for (int i = 0; i < 16; i++) {
        int nl = r * 16 + i;
        float acc = 0.0f;
        #pragma unroll
        for (int k4 = 0; k4 < 16; k4++) {
            float4 f = *(const float4*)&fsh[nl * F + k4 * 4];
            acc += f.x * wj[k4 * 4 + 0];
            acc += f.y * wj[k4 * 4 + 1];
            acc += f.z * wj[k4 * 4 + 2];
            acc += f.w * wj[k4 * 4 + 3];
        }
        int node = nb + nl;
        if (node < N_NODES) out[node * 64 + j] = acc;
    }
}

// ---------------- launch ----------------
extern "C" void kernel_launch(void* const* d_in, const int* in_sizes, int n_in,
                              void* d_out, int out_size) {
    const float* feat = (const float*)d_in[0];
    const float* W    = (const float*)d_in[1];
    const float* al   = (const float*)d_in[2];
    const float* ar   = (const float*)d_in[3];
    const int*   src  = (const int*)d_in[4];
    const int*   dst  = (const int*)d_in[5];
    float* out = (float*)d_out;

    k_init<<<(N_PAD * F + 255) / 256, 256>>>();
    k_elr<<<(N_NODES * 32 + 255) / 256, 256>>>(feat, al, ar);
    k_edge_max<<<(N_EDGES + 255) / 256, 256>>>(src, dst);
    k_edge_exp<<<(N_EDGES + 255) / 256, 256>>>(dst);
    k_recip<<<(N_NODES + 255) / 256, 256>>>();
    k_scatter<<<(N_EDGES * 16 + 255) / 256, 256>>>(feat, src, dst);
    k_gemm<<<N_PAD / 64, 256>>>(W, out);
}